// round 3
// baseline (speedup 1.0000x reference)
#include <cuda_runtime.h>

#define NB 64
#define NS 512
#define NH 1024
#define NT 21
#define FULLMASK 0xffffffffu

// Scratch: emissions [B, S, T] fp32 (2.75 MB)
__device__ float g_em[(size_t)NB * NS * NT];

__device__ __forceinline__ void fma2(unsigned long long& d, unsigned long long a,
                                     unsigned long long b) {
    asm("fma.rn.f32x2 %0, %1, %2, %0;" : "+l"(d) : "l"(a), "l"(b));
}

__device__ __forceinline__ float warpMaxF(float v) {
#pragma unroll
    for (int o = 16; o; o >>= 1) v = fmaxf(v, __shfl_xor_sync(FULLMASK, v, o));
    return v;
}
__device__ __forceinline__ float warpSumF(float v) {
#pragma unroll
    for (int o = 16; o; o >>= 1) v += __shfl_xor_sync(FULLMASK, v, o);
    return v;
}
__device__ __forceinline__ int warpSumI(int v) {
#pragma unroll
    for (int o = 16; o; o >>= 1) v += __shfl_xor_sync(FULLMASK, v, o);
    return v;
}

__global__ void init_out(float* out) { out[0] = 0.0f; }

// ---------------------------------------------------------------------------
// Emissions: out[row][t] = dot(hs[row], W[t]) + b[t]
// One thread per (b,s) row. W staged in smem (84 KB), packed f32x2 FMAs.
// ---------------------------------------------------------------------------
extern __shared__ unsigned char s_raw[];

__global__ __launch_bounds__(256) void emissions_kernel(
    const float* __restrict__ hs, const float* __restrict__ W,
    const float* __restrict__ bias) {
    float* sW = (float*)s_raw;
    {
        const float4* src = (const float4*)W;
        float4* dst = (float4*)sW;
        for (int i = threadIdx.x; i < NT * NH / 4; i += blockDim.x) dst[i] = src[i];
    }
    __syncthreads();

    int row = blockIdx.x * blockDim.x + threadIdx.x;  // 0..NB*NS-1

    unsigned long long acc[NT];
#pragma unroll
    for (int t = 0; t < NT; t++) acc[t] = 0ull;  // (0.0f, 0.0f)

    const ulonglong2* h4 = (const ulonglong2*)(hs + (size_t)row * NH);
#pragma unroll 2
    for (int i = 0; i < NH / 4; i++) {
        ulonglong2 a = h4[i];
#pragma unroll
        for (int t = 0; t < NT; t++) {
            ulonglong2 w = ((const ulonglong2*)(sW + t * NH))[i];
            fma2(acc[t], a.x, w.x);
            fma2(acc[t], a.y, w.y);
        }
    }
    float* out = g_em + (size_t)row * NT;
#pragma unroll
    for (int t = 0; t < NT; t++) {
        float lo = __uint_as_float((unsigned)(acc[t] & 0xffffffffull));
        float hi = __uint_as_float((unsigned)(acc[t] >> 32));
        out[t] = (lo + hi) + bias[t];
    }
}

// ---------------------------------------------------------------------------
// CRF: blocks 0..63 = forward (logZ + numerator -> loss), 64..127 = Viterbi.
// One warp per batch, lane j = state j (j < 21).
// ---------------------------------------------------------------------------
__global__ __launch_bounds__(32) void crf_kernel(
    const int* __restrict__ mask, const int* __restrict__ labels,
    const float* __restrict__ trans, const float* __restrict__ start,
    const float* __restrict__ endt, float* __restrict__ out) {
    int b = blockIdx.x & (NB - 1);
    int mode = blockIdx.x >> 6;
    int lane = threadIdx.x;
    int jj = lane < NT ? lane : NT - 1;  // clamped for safe loads
    bool act = lane < NT;

    const float* em = g_em + (size_t)b * NS * NT;
    const int* mb = mask + (size_t)b * NS;

    if (mode == 0) {
        // ---------------- Forward algorithm (scaled domain) ----------------
        // E_j holds exp(alpha_j - C). Per step:
        //   s_j = sum_i E_i * exp(trans[i][j]);  E'_j = s_j * exp(emit_j)
        // Renormalize (divide by max, add log to C) every 8 steps.
        float ETc[NT];
#pragma unroll
        for (int i = 0; i < NT; i++) ETc[i] = __expf(trans[i * NT + jj]);

        float alpha0 = start[jj] + em[jj];
        float a0 = act ? alpha0 : -1e30f;
        float m = warpMaxF(a0);
        float C = m;
        float E = act ? __expf(alpha0 - m) : 0.f;

        // 2-deep prefetch of emissions + mask
        float emit_a = em[1 * NT + jj];
        float emit_b = em[2 * NT + jj];
        int mk_a = mb[1], mk_b = mb[2];

        for (int t = 1; t < NS; t++) {
            float emit = emit_a;
            int mk = mk_a;
            emit_a = emit_b;
            mk_a = mk_b;
            if (t + 2 < NS) {
                emit_b = em[(t + 2) * NT + jj];
                mk_b = mb[t + 2];
            }
            if (mk) {
                float s0 = 0.f, s1 = 0.f, s2 = 0.f;
#pragma unroll
                for (int i = 0; i < NT; i += 3) {
                    s0 += __shfl_sync(FULLMASK, E, i) * ETc[i];
                    if (i + 1 < NT) s1 += __shfl_sync(FULLMASK, E, i + 1) * ETc[i + 1];
                    if (i + 2 < NT) s2 += __shfl_sync(FULLMASK, E, i + 2) * ETc[i + 2];
                }
                float s = (s0 + s1) + s2;
                E = act ? s * __expf(emit) : 0.f;
            }
            if ((t & 7) == 7) {
                float mx = warpMaxF(E);
                C += __logf(mx);
                E *= (1.0f / mx);
            }
        }
        float term = act ? E * __expf(endt[jj]) : 0.f;
        float ssum = warpSumF(term);
        float logZ = C + __logf(ssum);

        // ---------------- Numerator (gold-path score) ----------------
        const int* lb = labels + (size_t)b * NS;
        float num = 0.f;
        int msum = 0;
        for (int t = lane; t < NS; t += 32) {
            int lt = lb[t];
            msum += mb[t];
            float e = em[t * NT + lt];
            if (t == 0)
                num += start[lt] + e;
            else
                num += (trans[lb[t - 1] * NT + lt] + e) * (float)mb[t];
        }
        num = warpSumF(num);
        msum = warpSumI(msum);
        if (lane == 0) {
            int last = lb[msum - 1];
            num += endt[last];
            atomicAdd(out, logZ - num);  // loss contribution
        }
    } else {
        // ---------------- Viterbi ----------------
        __shared__ unsigned char bp[NS - 1][32];
        float trc[NT];
#pragma unroll
        for (int i = 0; i < NT; i++) trc[i] = trans[i * NT + jj];

        float sc = act ? start[jj] + em[jj] : -1e30f;

        float emit_a = em[1 * NT + jj];
        float emit_b = em[2 * NT + jj];
        int mk_a = mb[1], mk_b = mb[2];

        for (int t = 1; t < NS; t++) {
            float emit = emit_a;
            int mk = mk_a;
            emit_a = emit_b;
            mk_a = mk_b;
            if (t + 2 < NS) {
                emit_b = em[(t + 2) * NT + jj];
                mk_b = mb[t + 2];
            }
            float best = -1e30f;
            int arg = 0;
#pragma unroll
            for (int i = 0; i < NT; i++) {
                float v = __shfl_sync(FULLMASK, sc, i) + trc[i];
                if (v > best) { best = v; arg = i; }  // first-max tie-break
            }
            if (mk) {
                if (act) sc = best + emit;
                bp[t - 1][lane] = (unsigned char)arg;
            } else {
                bp[t - 1][lane] = (unsigned char)lane;  // identity
            }
        }
        __syncwarp();

        // argmax over final score + end, lowest index on ties
        float v = act ? sc + endt[jj] : -1e30f;
        int idx = lane;
#pragma unroll
        for (int o = 16; o; o >>= 1) {
            float ov = __shfl_xor_sync(FULLMASK, v, o);
            int oi = __shfl_xor_sync(FULLMASK, idx, o);
            if (ov > v || (ov == v && oi < idx)) { v = ov; idx = oi; }
        }

        if (lane == 0) {
            float* pred = out + 1 + (size_t)b * NS;
            int tag = idx;
            pred[NS - 1] = mb[NS - 1] ? (float)tag : 0.0f;
            for (int p = NS - 2; p >= 0; p--) {
                tag = bp[p][tag];
                pred[p] = mb[p] ? (float)tag : 0.0f;
            }
        }
    }
}

// ---------------------------------------------------------------------------
extern "C" void kernel_launch(void* const* d_in, const int* in_sizes, int n_in,
                              void* d_out, int out_size) {
    const float* hs = (const float*)d_in[0];     // hidden_states [B,S,H] f32
    const int* mask = (const int*)d_in[1];       // attention_mask [B,S] i32
    const int* labels = (const int*)d_in[2];     // labels [B,S] i32 (JAX x64 off)
    const float* W = (const float*)d_in[3];      // [T,H]
    const float* bias = (const float*)d_in[4];   // [T]
    const float* trans = (const float*)d_in[5];  // [T,T]
    const float* start = (const float*)d_in[6];  // [T]
    const float* endt = (const float*)d_in[7];   // [T]
    float* out = (float*)d_out;                  // [1 + B*S] f32

    cudaFuncSetAttribute(emissions_kernel,
                         cudaFuncAttributeMaxDynamicSharedMemorySize,
                         NT * NH * (int)sizeof(float));

    init_out<<<1, 1>>>(out);
    emissions_kernel<<<(NB * NS) / 256, 256, NT * NH * sizeof(float)>>>(hs, W, bias);
    crf_kernel<<<2 * NB, 32>>>(mask, labels, trans, start, endt, out);
}